// round 9
// baseline (speedup 1.0000x reference)
#include <cuda_runtime.h>

#define NS 4096
#define NBATCH 32
#define TPB 256
#define SROW 17   // padded smem row stride (16 feats + 1) to break bank conflicts

// pywt db4 dec filters, time-reversed (cross-correlation form)
__device__ __constant__ float cH0[8] = {
     0.23037781330885523f,  0.7148465705525415f,   0.6308807679295904f,
    -0.02798376941698385f, -0.18703481171888114f,  0.030841381835986965f,
     0.032883011666982945f, -0.010597401784997278f };
__device__ __constant__ float cH1[8] = {
    -0.010597401784997278f, -0.032883011666982945f, 0.030841381835986965f,
     0.18703481171888114f,  -0.02798376941698385f,  -0.6308807679295904f,
     0.7148465705525415f,   -0.23037781330885523f };

// Lowpass scratch planes, (B, T_k, 64) contiguous.
__device__ float g_scratch[8126464];
#define OFF_LO1 0
#define OFF_LO2 4194304
#define OFF_LO3 6291456
#define OFF_LO4 7340032
#define OFF_LO5 7864320

__device__ __forceinline__ int level_of(float sc) {
    int l = 2 + (int)rintf(sc * 3.0f);          // round-half-even, matches jnp.round
    return l < 2 ? 2 : (l > 5 ? 5 : l);
}

// ---------------- pure streaming zero-fill of all tails ----------------
// det1[s>=2048], hf[s>=2048], det2[s>=1024], det3[s>=512], det4[s>=256], det5[s>=128]
__global__ void __launch_bounds__(TPB)
zero_kernel(float4* __restrict__ out4)
{
    int idx = blockIdx.x * TPB + threadIdx.x;
    const int q = idx & 3;                       // quarter row (4 float4 = 64 B)
    const int s = (idx >> 2) & (NS - 1);
    const int b = idx >> 14;

    const size_t PLANE4 = (size_t)NBATCH * NS * 16;
    const size_t row4   = ((size_t)b * NS + s) * 16 + q * 4;
    const float4 z = make_float4(0.f, 0.f, 0.f, 0.f);

#define ZSTORE(p) { float4* pp = out4 + (size_t)(p) * PLANE4 + row4; \
                    pp[0] = z; pp[1] = z; pp[2] = z; pp[3] = z; }
    if (s >= 2048) { ZSTORE(1) ZSTORE(6) }
    if (s >= 1024) ZSTORE(2)
    if (s >=  512) ZSTORE(3)
    if (s >=  256) ZSTORE(4)
    if (s >=  128) ZSTORE(5)
#undef ZSTORE
}

// ---------------- level 1, coefficient rows only (n < 2048) ----------------
__global__ void __launch_bounds__(TPB)
conv1_kernel(const float* __restrict__ x, float* __restrict__ lo1,
             float* __restrict__ out)
{
    int idx = blockIdx.x * TPB + threadIdx.x;
    const int f4 = idx & 15;
    const int n  = (idx >> 4) & 2047;
    const int b  = idx >> 15;                    // 2048*16 per batch

    const float4* pin = (const float4*)x + (size_t)b * NS * 16 + f4;
    float4 lo = make_float4(0.f, 0.f, 0.f, 0.f);
    float4 hi = make_float4(0.f, 0.f, 0.f, 0.f);
#pragma unroll
    for (int t = 0; t < 8; ++t) {
        int r = 2 * n + t - 3;
        if (r >= 0 && r < NS) {
            float4 v = __ldg(pin + (size_t)r * 16);
            float c0 = cH0[t], c1 = cH1[t];
            lo.x = fmaf(c0, v.x, lo.x); lo.y = fmaf(c0, v.y, lo.y);
            lo.z = fmaf(c0, v.z, lo.z); lo.w = fmaf(c0, v.w, lo.w);
            hi.x = fmaf(c1, v.x, hi.x); hi.y = fmaf(c1, v.y, hi.y);
            hi.z = fmaf(c1, v.z, hi.z); hi.w = fmaf(c1, v.w, hi.w);
        }
    }
    const size_t PLANE4 = (size_t)NBATCH * NS * 16;
    const size_t row4   = ((size_t)b * NS + n) * 16 + f4;
    ((float4*)lo1)[((size_t)b * 2048 + n) * 16 + f4] = lo;
    ((float4*)out)[1 * PLANE4 + row4] = hi;      // det1 (always active)
    ((float4*)out)[6 * PLANE4 + row4] = hi;      // hf seed
}

// ---------------- level 2, coefficient rows only (n < 1024) ----------------
__global__ void __launch_bounds__(TPB)
conv2_kernel(const float* __restrict__ lo1, float* __restrict__ lo2,
             float* __restrict__ out)
{
    int idx = blockIdx.x * TPB + threadIdx.x;
    const int f4 = idx & 15;
    const int n  = (idx >> 4) & 1023;
    const int b  = idx >> 14;                    // 1024*16 per batch

    const float4* pin = (const float4*)lo1 + (size_t)b * 2048 * 16 + f4;
    float4 lo = make_float4(0.f, 0.f, 0.f, 0.f);
    float4 hi = make_float4(0.f, 0.f, 0.f, 0.f);
#pragma unroll
    for (int t = 0; t < 8; ++t) {
        int r = 2 * n + t - 3;
        if (r >= 0 && r < 2048) {
            float4 v = __ldg(pin + (size_t)r * 16);
            float c0 = cH0[t], c1 = cH1[t];
            lo.x = fmaf(c0, v.x, lo.x); lo.y = fmaf(c0, v.y, lo.y);
            lo.z = fmaf(c0, v.z, lo.z); lo.w = fmaf(c0, v.w, lo.w);
            hi.x = fmaf(c1, v.x, hi.x); hi.y = fmaf(c1, v.y, hi.y);
            hi.z = fmaf(c1, v.z, hi.z); hi.w = fmaf(c1, v.w, hi.w);
        }
    }
    const size_t PLANE4 = (size_t)NBATCH * NS * 16;
    const size_t row4   = ((size_t)b * NS + n) * 16 + f4;
    ((float4*)lo2)[((size_t)b * 1024 + n) * 16 + f4] = lo;
    ((float4*)out)[2 * PLANE4 + row4] = hi;      // det2 (always active, lf>=2)
    float4* ph = (float4*)out + 6 * PLANE4 + row4;   // L2-hot hf RMW
    float4 h = *ph;
    h.x += hi.x; h.y += hi.y; h.z += hi.z; h.w += hi.w;
    *ph = h;
}

// ---------------- fused levels 3+4+5 in shared memory ----------------
// CTA = (b, fg): 16 features fg*16..fg*16+15 of batch b. 128 CTAs.
__global__ void __launch_bounds__(TPB)
fuse345_kernel(const float* __restrict__ lo2g, float* __restrict__ lo3g,
               float* __restrict__ lo4g, float* __restrict__ lo5g,
               float* __restrict__ out, const float* __restrict__ scores)
{
    extern __shared__ float sm[];
    float* s2  = sm;                     // 1024*SROW
    float* s3  = s2 + 1024 * SROW;       // 512*SROW
    float* s4  = s3 +  512 * SROW;       // 256*SROW
    float* shf = s4 +  256 * SROW;       // 512*SROW

    const int b  = blockIdx.x >> 2;
    const int fg = blockIdx.x & 3;
    const int tid = threadIdx.x;
    const int c = tid & 3;               // fixed quarter of the 16-feat slice

    int lf[4];
#pragma unroll
    for (int j = 0; j < 4; ++j)
        lf[j] = level_of(__ldg(scores + fg * 16 + c * 4 + j));

    // load lo2 slice into smem
    for (int i = tid; i < 1024 * 4; i += TPB) {
        int s = i >> 2, cc = i & 3;
        const float* g = lo2g + ((size_t)b * 1024 + s) * 64 + fg * 16 + cc * 4;
        float* d = s2 + s * SROW + cc * 4;
        d[0] = g[0]; d[1] = g[1]; d[2] = g[2]; d[3] = g[3];
    }
    __syncthreads();

    const size_t PLANE4 = (size_t)NBATCH * NS * 16;

    // ---- level 3 (det idx 2): 512 outputs ----
    for (int i = tid; i < 512 * 4; i += TPB) {
        int n = i >> 2;
        float lo[4] = {0,0,0,0}, hi[4] = {0,0,0,0};
#pragma unroll
        for (int t = 0; t < 8; ++t) {
            int r = 2 * n + t - 3;
            if (r >= 0 && r < 1024) {
                const float* p = s2 + r * SROW + c * 4;
                float c0 = cH0[t], c1 = cH1[t];
#pragma unroll
                for (int j = 0; j < 4; ++j) {
                    lo[j] = fmaf(c0, p[j], lo[j]);
                    hi[j] = fmaf(c1, p[j], hi[j]);
                }
            }
        }
        float m[4];
#pragma unroll
        for (int j = 0; j < 4; ++j) m[j] = (2 < lf[j]) ? hi[j] : 0.f;
        float* pl = s3 + n * SROW + c * 4;
        float* ph = shf + n * SROW + c * 4;
#pragma unroll
        for (int j = 0; j < 4; ++j) { pl[j] = lo[j]; ph[j] = m[j]; }
        ((float4*)out)[3 * PLANE4 + ((size_t)b * NS + n) * 16 + fg * 4 + c] =
            make_float4(m[0], m[1], m[2], m[3]);
        ((float4*)lo3g)[((size_t)b * 512 + n) * 16 + fg * 4 + c] =
            make_float4(lo[0], lo[1], lo[2], lo[3]);
    }
    __syncthreads();

    // ---- level 4 (det idx 3): 256 outputs ----
    for (int i = tid; i < 256 * 4; i += TPB) {
        int n = i >> 2;
        float lo[4] = {0,0,0,0}, hi[4] = {0,0,0,0};
#pragma unroll
        for (int t = 0; t < 8; ++t) {
            int r = 2 * n + t - 3;
            if (r >= 0 && r < 512) {
                const float* p = s3 + r * SROW + c * 4;
                float c0 = cH0[t], c1 = cH1[t];
#pragma unroll
                for (int j = 0; j < 4; ++j) {
                    lo[j] = fmaf(c0, p[j], lo[j]);
                    hi[j] = fmaf(c1, p[j], hi[j]);
                }
            }
        }
        float m[4];
#pragma unroll
        for (int j = 0; j < 4; ++j) m[j] = (3 < lf[j]) ? hi[j] : 0.f;
        float* pl = s4 + n * SROW + c * 4;
        float* ph = shf + n * SROW + c * 4;
#pragma unroll
        for (int j = 0; j < 4; ++j) { pl[j] = lo[j]; ph[j] += m[j]; }
        ((float4*)out)[4 * PLANE4 + ((size_t)b * NS + n) * 16 + fg * 4 + c] =
            make_float4(m[0], m[1], m[2], m[3]);
        ((float4*)lo4g)[((size_t)b * 256 + n) * 16 + fg * 4 + c] =
            make_float4(lo[0], lo[1], lo[2], lo[3]);
    }
    __syncthreads();

    // ---- level 5 (det idx 4): 128 outputs ----
    for (int i = tid; i < 128 * 4; i += TPB) {
        int n = i >> 2;
        float lo[4] = {0,0,0,0}, hi[4] = {0,0,0,0};
#pragma unroll
        for (int t = 0; t < 8; ++t) {
            int r = 2 * n + t - 3;
            if (r >= 0 && r < 256) {
                const float* p = s4 + r * SROW + c * 4;
                float c0 = cH0[t], c1 = cH1[t];
#pragma unroll
                for (int j = 0; j < 4; ++j) {
                    lo[j] = fmaf(c0, p[j], lo[j]);
                    hi[j] = fmaf(c1, p[j], hi[j]);
                }
            }
        }
        float m[4];
#pragma unroll
        for (int j = 0; j < 4; ++j) m[j] = (4 < lf[j]) ? hi[j] : 0.f;
        float* ph = shf + n * SROW + c * 4;
#pragma unroll
        for (int j = 0; j < 4; ++j) ph[j] += m[j];
        ((float4*)out)[5 * PLANE4 + ((size_t)b * NS + n) * 16 + fg * 4 + c] =
            make_float4(m[0], m[1], m[2], m[3]);
        ((float4*)lo5g)[((size_t)b * 128 + n) * 16 + fg * 4 + c] =
            make_float4(lo[0], lo[1], lo[2], lo[3]);
    }
    __syncthreads();

    // ---- fold levels 3-5 detail into hf (s < 512), L2-hot RMW ----
    for (int i = tid; i < 512 * 4; i += TPB) {
        int n = i >> 2;
        float4* ph = (float4*)out + 6 * PLANE4 + ((size_t)b * NS + n) * 16 + fg * 4 + c;
        const float* sh = shf + n * SROW + c * 4;
        float4 h = *ph;
        h.x += sh[0]; h.y += sh[1]; h.z += sh[2]; h.w += sh[3];
        *ph = h;
    }
}

// ---------------- final: approx (plane 0) + low_freq (plane 7) ----------------
__global__ void __launch_bounds__(TPB)
final_kernel(float* __restrict__ out, const float* __restrict__ scores)
{
    int idx = blockIdx.x * TPB + threadIdx.x;
    const int f4 = idx & 15;
    const int s  = (idx >> 4) & (NS - 1);
    const int b  = idx >> 16;

    const size_t PLANE4 = (size_t)NBATCH * NS * 16;
    const size_t row4   = ((size_t)b * NS + s) * 16 + f4;

    const size_t offs[4] = { OFF_LO2, OFF_LO3, OFF_LO4, OFF_LO5 };
    const int f = f4 * 4;
    float av[4];
#pragma unroll
    for (int j = 0; j < 4; ++j) {
        int k = level_of(__ldg(scores + f + j)) - 2;     // 0..3
        int T = 1024 >> k;
        av[j] = (s < T)
            ? __ldg(g_scratch + offs[k] + ((size_t)b * T + s) * 64 + f + j)
            : 0.f;
    }
    float4 a = make_float4(av[0], av[1], av[2], av[3]);
    ((float4*)out)[row4] = a;               // approx
    ((float4*)out)[7 * PLANE4 + row4] = a;  // low_freq
}

extern "C" void kernel_launch(void* const* d_in, const int* in_sizes, int n_in,
                              void* d_out, int out_size)
{
    const float* x      = (const float*)d_in[0];
    const float* scores = (const float*)d_in[1];
    float* out          = (float*)d_out;

    float* scratch;
    cudaGetSymbolAddress((void**)&scratch, g_scratch);
    float* lo1 = scratch + OFF_LO1;
    float* lo2 = scratch + OFF_LO2;
    float* lo3 = scratch + OFF_LO3;
    float* lo4 = scratch + OFF_LO4;
    float* lo5 = scratch + OFF_LO5;

    const size_t fuse_smem = (size_t)(1024 + 512 + 256 + 512) * SROW * sizeof(float); // 156672
    cudaFuncSetAttribute(fuse345_kernel, cudaFuncAttributeMaxDynamicSharedMemorySize,
                         (int)fuse_smem);

    zero_kernel <<<(NBATCH * NS   *  4) / TPB, TPB>>>((float4*)out);
    conv1_kernel<<<(NBATCH * 2048 * 16) / TPB, TPB>>>(x, lo1, out);
    conv2_kernel<<<(NBATCH * 1024 * 16) / TPB, TPB>>>(lo1, lo2, out);
    fuse345_kernel<<<NBATCH * 4, TPB, fuse_smem>>>(lo2, lo3, lo4, lo5, out, scores);
    final_kernel<<<(NBATCH * NS * 16) / TPB, TPB>>>(out, scores);
}